// round 1
// baseline (speedup 1.0000x reference)
#include <cuda_runtime.h>
#include <cstdint>

// out[b,t,e] = tok_weight[x[b,t], e] + pos_weight[t, e]
// B=4, T=4096, E=512 (fp32). Pure HBM-bound gather + add.
//
// Layout: each row is 512 floats = 128 float4. Thread i handles one float4:
//   row = i >> 7  (which [b,t])
//   c   = i & 127 (which float4 within the embedding row)
// Fully coalesced: consecutive threads touch consecutive float4 of the same
// gathered row (2KB contiguous), so every 128B line is fully used.

__global__ void __launch_bounds__(256) pos_embed_kernel(
    const int* __restrict__ x,            // [B*T]
    const float4* __restrict__ tok_w,     // [VOCAB, 128] as float4
    const float4* __restrict__ pos_w,     // [TIME, 128] as float4
    float4* __restrict__ out,             // [B*T, 128] as float4
    int n_rows,                           // B*T
    int t_len)                            // T (for pos index = row % T)
{
    const long long total = (long long)n_rows * 128;
    long long i = (long long)blockIdx.x * blockDim.x + threadIdx.x;
    const long long stride = (long long)gridDim.x * blockDim.x;

    for (; i < total; i += stride) {
        int row = (int)(i >> 7);
        int c   = (int)(i & 127);
        int tok = __ldg(&x[row]);            // broadcast within half-warp via L1
        int t   = row & (t_len - 1);         // T = 4096 is a power of two
        float4 a = __ldg(&tok_w[(long long)tok * 128 + c]);
        float4 p = __ldg(&pos_w[(long long)t * 128 + c]);
        float4 r;
        r.x = a.x + p.x;
        r.y = a.y + p.y;
        r.z = a.z + p.z;
        r.w = a.w + p.w;
        out[i] = r;
    }
}

extern "C" void kernel_launch(void* const* d_in, const int* in_sizes, int n_in,
                              void* d_out, int out_size) {
    // Inputs per metadata order: x (int32 [B,T]), tok_weight (f32 [VOCAB,E]),
    // pos_weight (f32 [TIME,E]). Output f32 [B,T,E].
    const int*    x     = (const int*)d_in[0];
    const float4* tok_w = (const float4*)d_in[1];
    const float4* pos_w = (const float4*)d_in[2];
    float4*       out   = (float4*)d_out;

    const int n_rows = in_sizes[0];          // B*T = 16384
    const int T      = 4096;                 // fixed by problem

    const long long total = (long long)n_rows * 128;  // float4 count
    const int threads = 256;
    int blocks = (int)((total + threads - 1) / threads);
    // Cap grid; grid-stride handles the rest. 148 SMs * 8 CTAs is plenty.
    if (blocks > 8192) blocks = 8192;

    pos_embed_kernel<<<blocks, threads>>>(x, tok_w, pos_w, out, n_rows, T);
}

// round 2
// speedup vs baseline: 1.1348x; 1.1348x over previous
#include <cuda_runtime.h>
#include <cstdint>

// out[b,t,e] = tok_weight[x[b,t], e] + pos_weight[t, e]
// B=4, T=4096, E=512 fp32. One WARP per row; each lane handles 4 float4
// (columns lane, lane+32, lane+64, lane+96) -> 8 independent LDG.128 in
// flight per thread, x[row] loaded once per warp, index math amortized.

__global__ void __launch_bounds__(256) pos_embed_kernel(
    const int* __restrict__ x,            // [B*T]
    const float4* __restrict__ tok_w,     // [VOCAB, 128] as float4
    const float4* __restrict__ pos_w,     // [TIME, 128] as float4
    float4* __restrict__ out,             // [B*T, 128] as float4
    int n_rows)                           // B*T
{
    const int warps_per_blk = blockDim.x >> 5;
    int row  = blockIdx.x * warps_per_blk + (threadIdx.x >> 5);
    if (row >= n_rows) return;
    int lane = threadIdx.x & 31;

    int tok = __ldg(&x[row]);
    int t   = row & 4095;                 // T = 4096 (power of two)

    const float4* __restrict__ tp = tok_w + (long long)tok * 128 + lane;
    const float4* __restrict__ pp = pos_w + (long long)t   * 128 + lane;
    float4*       __restrict__ op = out   + (long long)row * 128 + lane;

    // 8 independent global loads -> high MLP, DRAM latency fully hidden
    float4 a0 = __ldg(tp +  0);
    float4 a1 = __ldg(tp + 32);
    float4 a2 = __ldg(tp + 64);
    float4 a3 = __ldg(tp + 96);
    float4 p0 = __ldg(pp +  0);
    float4 p1 = __ldg(pp + 32);
    float4 p2 = __ldg(pp + 64);
    float4 p3 = __ldg(pp + 96);

    float4 r0, r1, r2, r3;
    r0.x = a0.x + p0.x; r0.y = a0.y + p0.y; r0.z = a0.z + p0.z; r0.w = a0.w + p0.w;
    r1.x = a1.x + p1.x; r1.y = a1.y + p1.y; r1.z = a1.z + p1.z; r1.w = a1.w + p1.w;
    r2.x = a2.x + p2.x; r2.y = a2.y + p2.y; r2.z = a2.z + p2.z; r2.w = a2.w + p2.w;
    r3.x = a3.x + p3.x; r3.y = a3.y + p3.y; r3.z = a3.z + p3.z; r3.w = a3.w + p3.w;

    op[ 0] = r0;
    op[32] = r1;
    op[64] = r2;
    op[96] = r3;
}

extern "C" void kernel_launch(void* const* d_in, const int* in_sizes, int n_in,
                              void* d_out, int out_size) {
    const int*    x     = (const int*)d_in[0];
    const float4* tok_w = (const float4*)d_in[1];
    const float4* pos_w = (const float4*)d_in[2];
    float4*       out   = (float4*)d_out;

    const int n_rows = in_sizes[0];           // B*T = 16384
    const int threads = 256;                  // 8 warps -> 8 rows per block
    const int rows_per_blk = threads / 32;
    int blocks = (n_rows + rows_per_blk - 1) / rows_per_blk;   // 2048

    pos_embed_kernel<<<blocks, threads>>>(x, tok_w, pos_w, out, n_rows);
}

// round 3
// speedup vs baseline: 1.3821x; 1.2179x over previous
#include <cuda_runtime.h>
#include <cstdint>

// out[b,t,:] = tok_weight[x[b,t],:] + pos_weight[t,:]
// B=4, T=4096, E=512 fp32.
//
// One WARP per time-step t. The 4 batch rows (t, t+T, t+2T, t+3T) share
// pos_weight[t], which is loaded ONCE into registers. Work is split into two
// phases of 2 batches each to bound register pressure (~70 regs):
//   phase A: gather tok rows b0,b1 (8 LDG.128/thread) + pos (4) -> 8 STG
//   phase B: gather tok rows b2,b3 (pos reused from regs)       -> 8 STG
// All 4 x[] index loads hoisted to the top (single L2 latency for the chain).
// Output uses streaming stores (__stcs) so the 64MB tok table stays L2-resident
// across graph replays instead of being evicted by write allocation.

__global__ void __launch_bounds__(128) pos_embed_kernel(
    const int* __restrict__ x,            // [4*T]
    const float4* __restrict__ tok_w,     // [VOCAB, 128] float4
    const float4* __restrict__ pos_w,     // [T, 128] float4
    float4* __restrict__ out,             // [4*T, 128] float4
    int T)                                // 4096
{
    const int warps_per_blk = blockDim.x >> 5;
    int t = blockIdx.x * warps_per_blk + (threadIdx.x >> 5);
    if (t >= T) return;
    const int lane = threadIdx.x & 31;

    // Hoist all index loads: one latency, not four.
    const int tok0 = __ldg(&x[t]);
    const int tok1 = __ldg(&x[t + T]);
    const int tok2 = __ldg(&x[t + 2 * T]);
    const int tok3 = __ldg(&x[t + 3 * T]);

    const float4* __restrict__ pp = pos_w + (long long)t * 128 + lane;
    const float4* __restrict__ t0 = tok_w + (long long)tok0 * 128 + lane;
    const float4* __restrict__ t1 = tok_w + (long long)tok1 * 128 + lane;
    const float4* __restrict__ t2 = tok_w + (long long)tok2 * 128 + lane;
    const float4* __restrict__ t3 = tok_w + (long long)tok3 * 128 + lane;
    float4* __restrict__ o0 = out + (long long)t * 128 + lane;            // b=0
    float4* __restrict__ o1 = o0 + (long long)T * 128;                    // b=1
    float4* __restrict__ o2 = o1 + (long long)T * 128;                    // b=2
    float4* __restrict__ o3 = o2 + (long long)T * 128;                    // b=3

    // pos row lives in registers for the whole warp lifetime (16 regs)
    float4 p0 = __ldg(pp +  0);
    float4 p1 = __ldg(pp + 32);
    float4 p2 = __ldg(pp + 64);
    float4 p3 = __ldg(pp + 96);

    // ---- phase A: batches 0,1 (8 independent gathers in flight) ----
    float4 a0 = __ldg(t0 +  0), a1 = __ldg(t0 + 32), a2 = __ldg(t0 + 64), a3 = __ldg(t0 + 96);
    float4 b0 = __ldg(t1 +  0), b1 = __ldg(t1 + 32), b2 = __ldg(t1 + 64), b3 = __ldg(t1 + 96);

    float4 r;
    r.x = a0.x + p0.x; r.y = a0.y + p0.y; r.z = a0.z + p0.z; r.w = a0.w + p0.w; __stcs(o0 +  0, r);
    r.x = a1.x + p1.x; r.y = a1.y + p1.y; r.z = a1.z + p1.z; r.w = a1.w + p1.w; __stcs(o0 + 32, r);
    r.x = a2.x + p2.x; r.y = a2.y + p2.y; r.z = a2.z + p2.z; r.w = a2.w + p2.w; __stcs(o0 + 64, r);
    r.x = a3.x + p3.x; r.y = a3.y + p3.y; r.z = a3.z + p3.z; r.w = a3.w + p3.w; __stcs(o0 + 96, r);

    r.x = b0.x + p0.x; r.y = b0.y + p0.y; r.z = b0.z + p0.z; r.w = b0.w + p0.w; __stcs(o1 +  0, r);
    r.x = b1.x + p1.x; r.y = b1.y + p1.y; r.z = b1.z + p1.z; r.w = b1.w + p1.w; __stcs(o1 + 32, r);
    r.x = b2.x + p2.x; r.y = b2.y + p2.y; r.z = b2.z + p2.z; r.w = b2.w + p2.w; __stcs(o1 + 64, r);
    r.x = b3.x + p3.x; r.y = b3.y + p3.y; r.z = b3.z + p3.z; r.w = b3.w + p3.w; __stcs(o1 + 96, r);

    // ---- phase B: batches 2,3 (pos reused from registers) ----
    float4 c0 = __ldg(t2 +  0), c1 = __ldg(t2 + 32), c2 = __ldg(t2 + 64), c3 = __ldg(t2 + 96);
    float4 d0 = __ldg(t3 +  0), d1 = __ldg(t3 + 32), d2 = __ldg(t3 + 64), d3 = __ldg(t3 + 96);

    r.x = c0.x + p0.x; r.y = c0.y + p0.y; r.z = c0.z + p0.z; r.w = c0.w + p0.w; __stcs(o2 +  0, r);
    r.x = c1.x + p1.x; r.y = c1.y + p1.y; r.z = c1.z + p1.z; r.w = c1.w + p1.w; __stcs(o2 + 32, r);
    r.x = c2.x + p2.x; r.y = c2.y + p2.y; r.z = c2.z + p2.z; r.w = c2.w + p2.w; __stcs(o2 + 64, r);
    r.x = c3.x + p3.x; r.y = c3.y + p3.y; r.z = c3.z + p3.z; r.w = c3.w + p3.w; __stcs(o2 + 96, r);

    r.x = d0.x + p0.x; r.y = d0.y + p0.y; r.z = d0.z + p0.z; r.w = d0.w + p0.w; __stcs(o3 +  0, r);
    r.x = d1.x + p1.x; r.y = d1.y + p1.y; r.z = d1.z + p1.z; r.w = d1.w + p1.w; __stcs(o3 + 32, r);
    r.x = d2.x + p2.x; r.y = d2.y + p2.y; r.z = d2.z + p2.z; r.w = d2.w + p2.w; __stcs(o3 + 64, r);
    r.x = d3.x + p3.x; r.y = d3.y + p3.y; r.z = d3.z + p3.z; r.w = d3.w + p3.w; __stcs(o3 + 96, r);
}

extern "C" void kernel_launch(void* const* d_in, const int* in_sizes, int n_in,
                              void* d_out, int out_size) {
    const int*    x     = (const int*)d_in[0];
    const float4* tok_w = (const float4*)d_in[1];
    const float4* pos_w = (const float4*)d_in[2];
    float4*       out   = (float4*)d_out;

    const int T = 4096;                       // fixed problem shape (B=4)
    const int threads = 128;                  // 4 warps -> 4 time-steps/block
    const int warps_per_blk = threads / 32;
    int blocks = (T + warps_per_blk - 1) / warps_per_blk;   // 1024

    pos_embed_kernel<<<blocks, threads>>>(x, tok_w, pos_w, out, T);
}